// round 12
// baseline (speedup 1.0000x reference)
#include <cuda_runtime.h>
#include <cuda_fp16.h>
#include <cstdint>

#define SCALE 0.05103103630798288f   // 384^-0.5
#define STG2_QK 15360                 // A 5120 (64x80B) + B 10240 (128x80B)
#define STG2_T  13824                 // A 5120 + B 8704 (32x272B)
#define SMEM2_QK (3 * STG2_QK)        // 46080
#define SMEM2_T  (3 * STG2_T)         // 41472
#define SMEM2_PV (SMEM2_T + 16384)    // + sg[64 groups][64 rows] fp32

__device__ __half g_Wh[3 * 384 * 384];           // W[k][n] fp16, Wq pre-scaled
__device__ __half g_Qh[16 * 2048 * 384];
__device__ __half g_Kh[16 * 2048 * 384];
__device__ __half g_Vh[16 * 2048 * 384];
__device__ __half g_Pt[16ll * 2048 * 2048];      // P~ = exp(S - m_grp), fp16
__device__ float  g_mt[16 * 64 * 2048];          // [b][group(32 keys)][row]
__device__ float  g_lt[16 * 64 * 2048];

__device__ __forceinline__ uint32_t smem_u32(const void* p) {
    uint32_t a;
    asm("{ .reg .u64 t; cvta.to.shared.u64 t, %1; cvt.u32.u64 %0, t; }" : "=r"(a) : "l"(p));
    return a;
}
__device__ __forceinline__ void ldsm4(uint32_t addr, uint32_t* r) {
    asm volatile("ldmatrix.sync.aligned.m8n8.x4.shared.b16 {%0,%1,%2,%3}, [%4];"
        : "=r"(r[0]), "=r"(r[1]), "=r"(r[2]), "=r"(r[3]) : "r"(addr));
}
__device__ __forceinline__ void ldsm4t(uint32_t addr, uint32_t* r) {
    asm volatile("ldmatrix.sync.aligned.m8n8.x4.trans.shared.b16 {%0,%1,%2,%3}, [%4];"
        : "=r"(r[0]), "=r"(r[1]), "=r"(r[2]), "=r"(r[3]) : "r"(addr));
}
__device__ __forceinline__ void mmah(float* c, const uint32_t* a, const uint32_t* b) {
    asm volatile("mma.sync.aligned.m16n8k16.row.col.f32.f16.f16.f32 "
        "{%0,%1,%2,%3}, {%4,%5,%6,%7}, {%8,%9}, {%0,%1,%2,%3};"
        : "+f"(c[0]), "+f"(c[1]), "+f"(c[2]), "+f"(c[3])
        : "r"(a[0]), "r"(a[1]), "r"(a[2]), "r"(a[3]), "r"(b[0]), "r"(b[1]));
}

#define ACC_DECL()                                   \
    float acc[2][4][4];                              \
    _Pragma("unroll") for (int i_ = 0; i_ < 2; i_++) \
    _Pragma("unroll") for (int j_ = 0; j_ < 4; j_++) \
    _Pragma("unroll") for (int q_ = 0; q_ < 4; q_++) acc[i_][j_][q_] = 0.f;

// 8 warps: wm = wid&1 (2 x 32 rows), wn = wid>>1 (4 x 32 cols)
#define AOFF(wm, lane) ((uint32_t)(((wm) * 32 + ((lane) & 15)) * 80 + ((lane) >> 4) * 16))
#define BOFF(wn, lane) ((uint32_t)(((wn) * 32 + (((lane) >> 4) & 1) * 8 + ((lane) & 7)) * 80 + \
                                   (((lane) >> 3) & 1) * 16))
#define BOFFT(wn, lane) ((uint32_t)(((((lane) >> 3) & 1) * 8 + ((lane) & 7)) * 272 + \
                                    ((wn) * 32 + (((lane) >> 4) & 1) * 8) * 2))

// K-major 1-pass chunk: A@0 (64x80B), B@5120 (128x80B)
__device__ __forceinline__ void chunk1(uint32_t sbase, uint32_t aOff, uint32_t bOff,
                                       float acc[2][4][4]) {
#pragma unroll
    for (int ks = 0; ks < 2; ks++) {
        uint32_t a[2][4], b[4][2];
#pragma unroll
        for (int mf = 0; mf < 2; mf++) ldsm4(sbase + aOff + mf * 1280 + ks * 32, a[mf]);
#pragma unroll
        for (int n2 = 0; n2 < 2; n2++) {
            uint32_t r[4];
            ldsm4(sbase + 5120 + bOff + n2 * 1280 + ks * 32, r);
            b[n2 * 2][0] = r[0]; b[n2 * 2][1] = r[1];
            b[n2 * 2 + 1][0] = r[2]; b[n2 * 2 + 1][1] = r[3];
        }
#pragma unroll
        for (int mf = 0; mf < 2; mf++)
#pragma unroll
            for (int nf = 0; nf < 4; nf++) mmah(acc[mf][nf], a[mf], b[nf]);
    }
}

// MN-major-B chunk: A@0 (64x80B), B@5120 (32 rows x 272B), ldsm.trans.
// If SCALED, scale A fragments by per-row g (ga rows r, gb rows r+8).
template <bool SCALED>
__device__ __forceinline__ void chunk1t(uint32_t sbase, uint32_t aOff, uint32_t bOff,
                                        float acc[2][4][4],
                                        const __half2* ga, const __half2* gb) {
#pragma unroll
    for (int ks = 0; ks < 2; ks++) {
        uint32_t a[2][4], b[4][2];
#pragma unroll
        for (int mf = 0; mf < 2; mf++) {
            ldsm4(sbase + aOff + mf * 1280 + ks * 32, a[mf]);
            if (SCALED) {
                __half2* ap = reinterpret_cast<__half2*>(a[mf]);
                ap[0] = __hmul2(ap[0], ga[mf]);
                ap[2] = __hmul2(ap[2], ga[mf]);
                ap[1] = __hmul2(ap[1], gb[mf]);
                ap[3] = __hmul2(ap[3], gb[mf]);
            }
        }
#pragma unroll
        for (int n2 = 0; n2 < 2; n2++) {
            uint32_t r[4];
            ldsm4t(sbase + 5120 + bOff + (uint32_t)(ks * 16 * 272 + n2 * 32), r);
            b[n2 * 2][0] = r[0]; b[n2 * 2][1] = r[1];
            b[n2 * 2 + 1][0] = r[2]; b[n2 * 2 + 1][1] = r[3];
        }
#pragma unroll
        for (int mf = 0; mf < 2; mf++)
#pragma unroll
            for (int nf = 0; nf < 4; nf++) mmah(acc[mf][nf], a[mf], b[nf]);
    }
}

struct __align__(8) hpair { __half2 a, b; };
__device__ __forceinline__ hpair to_h(float4 v) {
    hpair r; r.a = __floats2half2_rn(v.x, v.y); r.b = __floats2half2_rn(v.z, v.w); return r;
}

// ---------------- cvtw: W fp32 -> fp16 (SCALE folded into Wq) ----------------
__global__ void cvtw_kernel(const float* __restrict__ Wq, const float* __restrict__ Wk,
                            const float* __restrict__ Wv) {
    int i = (blockIdx.x * 256 + threadIdx.x) * 4;
    int z = i / 147456, r = i - z * 147456;
    const float* W = (z == 0) ? Wq : ((z == 1) ? Wk : Wv);
    float4 v = *(const float4*)(W + r);
    float s = (z == 0) ? SCALE : 1.f;
    v.x *= s; v.y *= s; v.z *= s; v.w *= s;
    *(hpair*)&g_Wh[i] = to_h(v);
}

// ---------------- proj: 64x128 tile, 3 CTAs/SM ----------------
__global__ void __launch_bounds__(256, 3) proj_kernel(const float* __restrict__ X) {
    extern __shared__ char smem[];
    int tid = threadIdx.x, lane = tid & 31, wid = tid >> 5, wm = wid & 1, wn = wid >> 1;
    uint32_t sb = smem_u32(smem);
    int nt = blockIdx.x * 128, mt = blockIdx.y * 64, z = blockIdx.z;
    const float*  gA = X + (size_t)mt * 384;
    const __half* gW = g_Wh + (size_t)z * 147456 + nt;
    ACC_DECL();

    float4 va[2]; uint4 wb[2];
    auto ldg = [&](int c) {
#pragma unroll
        for (int i = 0; i < 2; i++) {
            int lin = tid + 256 * i, row = lin >> 3, c4 = (lin & 7) * 4;   // 64 x 32 fp32
            va[i] = *(const float4*)(gA + (size_t)row * 384 + c * 32 + c4);
            int r2 = lin >> 4, c2 = (lin & 15) * 8;                        // 32 x 128 fp16
            wb[i] = *(const uint4*)(gW + (size_t)(c * 32 + r2) * 384 + c2);
        }
    };
    auto stg = [&](char* buf) {
#pragma unroll
        for (int i = 0; i < 2; i++) {
            int lin = tid + 256 * i, row = lin >> 3, c4 = (lin & 7) * 4;
            *(hpair*)(buf + row * 80 + c4 * 2) = to_h(va[i]);
            int r2 = lin >> 4, c2 = (lin & 15) * 8;
            *(uint4*)(buf + 5120 + r2 * 272 + c2 * 2) = wb[i];
        }
    };
    uint32_t aOff = AOFF(wm, lane), bOff = BOFFT(wn, lane);
    ldg(0); stg(smem); ldg(1);
    __syncthreads();
    int rs = 0;
    for (int c = 0; c < 12; c++) {
        int ws = (rs == 2) ? 0 : rs + 1;
        if (c + 1 < 12) stg(smem + ws * STG2_T);
        if (c + 2 < 12) ldg(c + 2);
        chunk1t<false>(sb + (uint32_t)(rs * STG2_T), aOff, bOff, acc, 0, 0);
        __syncthreads();
        rs = ws;
    }

    __half* Yh = (z == 0) ? g_Qh : ((z == 1) ? g_Kh : g_Vh);
#pragma unroll
    for (int mf = 0; mf < 2; mf++)
#pragma unroll
        for (int h = 0; h < 2; h++) {
            int row = mt + wm * 32 + mf * 16 + (lane >> 2) + h * 8;
#pragma unroll
            for (int nf = 0; nf < 4; nf++) {
                int col = nt + wn * 32 + nf * 8 + (lane & 3) * 2;
                *(__half2*)&Yh[(size_t)row * 384 + col] =
                    __floats2half2_rn(acc[mf][nf][h * 2], acc[mf][nf][h * 2 + 1]);
            }
        }
}

// ---------------- qk: 64x128 tile, per-32col-group stats, no epilogue syncs ----------------
__global__ void __launch_bounds__(256, 3) qk_kernel() {
    extern __shared__ char smem[];
    int tid = threadIdx.x, lane = tid & 31, wid = tid >> 5, wm = wid & 1, wn = wid >> 1;
    uint32_t sb = smem_u32(smem);
    int b = blockIdx.y, r_ = (int)gridDim.x - 1 - (int)blockIdx.x;   // big qt2 first
    int qt2 = 0;
    while (r_ >= (qt2 >> 1) + 1) { r_ -= (qt2 >> 1) + 1; qt2++; }
    int kt = r_;
    size_t qb = ((size_t)b * 2048 + qt2 * 64) * 384;
    size_t kb = ((size_t)b * 2048 + kt * 128) * 384;
    ACC_DECL();

    uint4 rva; uint4 rvb[2];
    auto ldg = [&](int c) {
        int rr = tid >> 2, cc = (tid & 3) * 8;                    // A: 64 x 32
        rva = *(const uint4*)(g_Qh + qb + (size_t)rr * 384 + c * 32 + cc);
#pragma unroll
        for (int i = 0; i < 2; i++) {
            int lin = tid + 256 * i, r2 = lin >> 2, c2 = (lin & 3) * 8;   // B: 128 x 32
            rvb[i] = *(const uint4*)(g_Kh + kb + (size_t)r2 * 384 + c * 32 + c2);
        }
    };
    auto stg = [&](char* buf) {
        int rr = tid >> 2, cc = (tid & 3) * 8;
        *(uint4*)(buf + rr * 80 + cc * 2) = rva;
#pragma unroll
        for (int i = 0; i < 2; i++) {
            int lin = tid + 256 * i, r2 = lin >> 2, c2 = (lin & 3) * 8;
            *(uint4*)(buf + 5120 + r2 * 80 + c2 * 2) = rvb[i];
        }
    };
    uint32_t aOff = AOFF(wm, lane), bOff = BOFF(wn, lane);
    ldg(0); stg(smem); ldg(1);
    __syncthreads();
    int rs = 0;
    for (int c = 0; c < 12; c++) {
        int ws = (rs == 2) ? 0 : rs + 1;
        if (c + 1 < 12) stg(smem + ws * STG2_QK);
        if (c + 2 < 12) ldg(c + 2);
        chunk1(sb + (uint32_t)(rs * STG2_QK), aOff, bOff, acc);
        __syncthreads();
        rs = ws;
    }

    // ---- epilogue: mask, per-group (32-col) max/exp/sum, P~ store ----
    float pm[2][2] = {{-1e30f, -1e30f}, {-1e30f, -1e30f}};
#pragma unroll
    for (int mf = 0; mf < 2; mf++)
#pragma unroll
        for (int nf = 0; nf < 4; nf++)
#pragma unroll
            for (int q = 0; q < 4; q++) {
                int h = q >> 1;
                int qg = qt2 * 64 + wm * 32 + mf * 16 + (lane >> 2) + h * 8;
                int kg = kt * 128 + wn * 32 + nf * 8 + (lane & 3) * 2 + (q & 1);
                if (kg > qg) acc[mf][nf][q] = -1e30f;
                pm[mf][h] = fmaxf(pm[mf][h], acc[mf][nf][q]);
            }
    float ps[2][2] = {{0.f, 0.f}, {0.f, 0.f}};
#pragma unroll
    for (int mf = 0; mf < 2; mf++)
#pragma unroll
        for (int h = 0; h < 2; h++) {
            pm[mf][h] = fmaxf(pm[mf][h], __shfl_xor_sync(~0u, pm[mf][h], 1));
            pm[mf][h] = fmaxf(pm[mf][h], __shfl_xor_sync(~0u, pm[mf][h], 2));
        }
#pragma unroll
    for (int mf = 0; mf < 2; mf++)
#pragma unroll
        for (int nf = 0; nf < 4; nf++)
#pragma unroll
            for (int q = 0; q < 4; q++) {
                int h = q >> 1;
                float p = __expf(acc[mf][nf][q] - pm[mf][h]);
                acc[mf][nf][q] = p;
                ps[mf][h] += p;
            }
#pragma unroll
    for (int mf = 0; mf < 2; mf++)
#pragma unroll
        for (int h = 0; h < 2; h++) {
            ps[mf][h] += __shfl_xor_sync(~0u, ps[mf][h], 1);
            ps[mf][h] += __shfl_xor_sync(~0u, ps[mf][h], 2);
        }
    // stats: [b][group][row], group = kt*4 + wn
    size_t statb = ((size_t)b * 64 + kt * 4 + wn) * 2048 + qt2 * 64;
    if ((lane & 3) == 0)
#pragma unroll
        for (int mf = 0; mf < 2; mf++)
#pragma unroll
            for (int h = 0; h < 2; h++) {
                int rl = wm * 32 + mf * 16 + (lane >> 2) + h * 8;
                g_mt[statb + rl] = pm[mf][h];
                g_lt[statb + rl] = ps[mf][h];
            }
    __half* Prow = g_Pt + ((size_t)b * 2048 + qt2 * 64) * 2048 + (size_t)kt * 128;
#pragma unroll
    for (int mf = 0; mf < 2; mf++)
#pragma unroll
        for (int h = 0; h < 2; h++) {
            int rl = wm * 32 + mf * 16 + (lane >> 2) + h * 8;
#pragma unroll
            for (int nf = 0; nf < 4; nf++) {
                int col = wn * 32 + nf * 8 + (lane & 3) * 2;
                *(__half2*)&Prow[(size_t)rl * 2048 + col] =
                    __floats2half2_rn(acc[mf][nf][h * 2], acc[mf][nf][h * 2 + 1]);
            }
        }
}

// ---------------- pv: 64x128 tile; fused norm; g per chunk on A fragments ----------------
__global__ void __launch_bounds__(256, 3) pv_kernel(float* __restrict__ out) {
    extern __shared__ char smem[];
    int tid = threadIdx.x, lane = tid & 31, wid = tid >> 5, wm = wid & 1, wn = wid >> 1;
    uint32_t sb = smem_u32(smem);
    int nt = blockIdx.x * 128, qt2 = 31 - (int)blockIdx.y, b = blockIdx.z;
    int nch = (qt2 + 1) * 2;             // 32-key chunks == stat groups
    const __half* Pb = g_Pt + ((size_t)b * 2048 + qt2 * 64) * 2048;
    const __half* Vh = g_Vh + (size_t)b * 2048 * 384 + nt;
    float* sg = (float*)(smem + SMEM2_T);        // [64 groups][64 rows]
    ACC_DECL();

    uint4 rva; uint4 rvb[2];
    auto ldg = [&](int c) {
        int rr = tid >> 2, cc = (tid & 3) * 8;                    // A: 64 x 32
        rva = *(const uint4*)(Pb + (size_t)rr * 2048 + c * 32 + cc);
#pragma unroll
        for (int i = 0; i < 2; i++) {
            int lin = tid + 256 * i, r2 = lin >> 4, c2 = (lin & 15) * 8;  // B: 32 x 128
            rvb[i] = *(const uint4*)(Vh + (size_t)(c * 32 + r2) * 384 + c2);
        }
    };
    auto stg = [&](char* buf) {
        int rr = tid >> 2, cc = (tid & 3) * 8;
        *(uint4*)(buf + rr * 80 + cc * 2) = rva;
#pragma unroll
        for (int i = 0; i < 2; i++) {
            int lin = tid + 256 * i, r2 = lin >> 4, c2 = (lin & 15) * 8;
            *(uint4*)(buf + 5120 + r2 * 272 + c2 * 2) = rvb[i];
        }
    };
    uint32_t aOff = AOFF(wm, lane), bOff = BOFFT(wn, lane);
    ldg(0);
    // fused norm: fold factors for this CTA's 64 rows (overlaps ldg latency)
    if (tid < 64) {
        size_t base = ((size_t)b * 64) * 2048 + qt2 * 64 + tid;
        float m = -1e30f;
        for (int t = 0; t < nch; t++) m = fmaxf(m, g_mt[base + (size_t)t * 2048]);
        float l = 0.f;
        for (int t = 0; t < nch; t++)
            l += __expf(g_mt[base + (size_t)t * 2048] - m) * g_lt[base + (size_t)t * 2048];
        float inv = 1.f / l;
        for (int t = 0; t < nch; t++)
            sg[t * 64 + tid] = __expf(g_mt[base + (size_t)t * 2048] - m) * inv;
    }
    stg(smem); ldg(1);
    __syncthreads();

    int rbase = wm * 32 + (lane >> 2);
    int rs = 0;
    for (int c = 0; c < nch; c++) {
        __half2 ga[2], gb[2];
        const float* gp = sg + c * 64;
#pragma unroll
        for (int mf = 0; mf < 2; mf++) {
            ga[mf] = __float2half2_rn(gp[rbase + mf * 16]);
            gb[mf] = __float2half2_rn(gp[rbase + mf * 16 + 8]);
        }
        int ws = (rs == 2) ? 0 : rs + 1;
        if (c + 1 < nch) stg(smem + ws * STG2_T);
        if (c + 2 < nch) ldg(c + 2);
        chunk1t<true>(sb + (uint32_t)(rs * STG2_T), aOff, bOff, acc, ga, gb);
        __syncthreads();
        rs = ws;
    }

    float* Y = out + ((size_t)b * 2048 + qt2 * 64) * 384 + nt;
#pragma unroll
    for (int mf = 0; mf < 2; mf++)
#pragma unroll
        for (int h = 0; h < 2; h++) {
            int row = wm * 32 + mf * 16 + (lane >> 2) + h * 8;
#pragma unroll
            for (int nf = 0; nf < 4; nf++) {
                float2 v = make_float2(acc[mf][nf][h * 2], acc[mf][nf][h * 2 + 1]);
                *(float2*)&Y[(size_t)row * 384 + wn * 32 + nf * 8 + (lane & 3) * 2] = v;
            }
        }
}

extern "C" void kernel_launch(void* const* d_in, const int* in_sizes, int n_in,
                              void* d_out, int out_size) {
    const float* x  = (const float*)d_in[0];
    const float* Wq = (const float*)d_in[1];
    const float* Wk = (const float*)d_in[2];
    const float* Wv = (const float*)d_in[3];
    float* out = (float*)d_out;
    (void)in_sizes; (void)n_in; (void)out_size;

    cudaFuncSetAttribute(proj_kernel, cudaFuncAttributeMaxDynamicSharedMemorySize, SMEM2_T);
    cudaFuncSetAttribute(qk_kernel,   cudaFuncAttributeMaxDynamicSharedMemorySize, SMEM2_QK);
    cudaFuncSetAttribute(pv_kernel,   cudaFuncAttributeMaxDynamicSharedMemorySize, SMEM2_PV);

    cvtw_kernel<<<432, 256>>>(Wq, Wk, Wv);
    proj_kernel<<<dim3(3, 512, 3), 256, SMEM2_T>>>(x);
    qk_kernel<<<dim3(272, 16), 256, SMEM2_QK>>>();   // sum over qt2 of (qt2/2+1)
    pv_kernel<<<dim3(3, 32, 16), 256, SMEM2_PV>>>(out);
}

// round 13
// speedup vs baseline: 1.0968x; 1.0968x over previous
#include <cuda_runtime.h>
#include <cuda_fp16.h>
#include <cstdint>

#define SCALE 0.05103103630798288f   // 384^-0.5
#define STG_QK 20480                  // A 10240 + B 10240 (K-major)
#define STG_T  18944                  // A 10240 + B 8704  (MN-major B)
#define SMEM_QK3 (3 * STG_QK)         // 61440
#define SMEM_T3  (3 * STG_T)          // 56832
#define SMEM_PV3 (SMEM_T3 + 16384)    // + sg[32 groups][128 rows] fp32

__device__ __half g_Wh[3 * 384 * 384];           // W[k][n] fp16, Wq pre-scaled
__device__ __half g_Qh[16 * 2048 * 384];
__device__ __half g_Kh[16 * 2048 * 384];
__device__ __half g_Vh[16 * 2048 * 384];
__device__ __half g_Pt[16ll * 2048 * 2048];      // P~ = exp(S - m_grp), fp16
__device__ float  g_mt[16 * 32 * 2048];          // [b][group(64 keys)][qrow]
__device__ float  g_lt[16 * 32 * 2048];

__device__ __forceinline__ uint32_t smem_u32(const void* p) {
    uint32_t a;
    asm("{ .reg .u64 t; cvta.to.shared.u64 t, %1; cvt.u32.u64 %0, t; }" : "=r"(a) : "l"(p));
    return a;
}
__device__ __forceinline__ void ldsm4(uint32_t addr, uint32_t* r) {
    asm volatile("ldmatrix.sync.aligned.m8n8.x4.shared.b16 {%0,%1,%2,%3}, [%4];"
        : "=r"(r[0]), "=r"(r[1]), "=r"(r[2]), "=r"(r[3]) : "r"(addr));
}
__device__ __forceinline__ void ldsm4t(uint32_t addr, uint32_t* r) {
    asm volatile("ldmatrix.sync.aligned.m8n8.x4.trans.shared.b16 {%0,%1,%2,%3}, [%4];"
        : "=r"(r[0]), "=r"(r[1]), "=r"(r[2]), "=r"(r[3]) : "r"(addr));
}
__device__ __forceinline__ void mmah(float* c, const uint32_t* a, const uint32_t* b) {
    asm volatile("mma.sync.aligned.m16n8k16.row.col.f32.f16.f16.f32 "
        "{%0,%1,%2,%3}, {%4,%5,%6,%7}, {%8,%9}, {%0,%1,%2,%3};"
        : "+f"(c[0]), "+f"(c[1]), "+f"(c[2]), "+f"(c[3])
        : "r"(a[0]), "r"(a[1]), "r"(a[2]), "r"(a[3]), "r"(b[0]), "r"(b[1]));
}

#define ACC_DECL()                                   \
    float acc[2][8][4];                              \
    _Pragma("unroll") for (int i_ = 0; i_ < 2; i_++) \
    _Pragma("unroll") for (int j_ = 0; j_ < 8; j_++) \
    _Pragma("unroll") for (int q_ = 0; q_ < 4; q_++) acc[i_][j_][q_] = 0.f;

#define AOFF(wm, lane) ((uint32_t)(((wm) * 32 + ((lane) & 15)) * 80 + ((lane) >> 4) * 16))
#define BOFF(wn, lane) ((uint32_t)(((wn) * 64 + (((lane) >> 4) & 1) * 8 + ((lane) & 7)) * 80 + \
                                   (((lane) >> 3) & 1) * 16))
#define BOFFT(wn, lane) ((uint32_t)(((((lane) >> 3) & 1) * 8 + ((lane) & 7)) * 272 + \
                                    ((wn) * 64 + (((lane) >> 4) & 1) * 8) * 2))

// K-major 1-pass chunk: A@0 (80B stride), B@10240 (80B stride)
__device__ __forceinline__ void chunk1(uint32_t sbase, uint32_t aOff, uint32_t bOff,
                                       float acc[2][8][4]) {
#pragma unroll
    for (int ks = 0; ks < 2; ks++) {
        uint32_t a[2][4], b[8][2];
#pragma unroll
        for (int mf = 0; mf < 2; mf++) ldsm4(sbase + aOff + mf * 1280 + ks * 32, a[mf]);
#pragma unroll
        for (int n2 = 0; n2 < 4; n2++) {
            uint32_t r[4];
            ldsm4(sbase + 10240 + bOff + n2 * 1280 + ks * 32, r);
            b[n2 * 2][0] = r[0]; b[n2 * 2][1] = r[1];
            b[n2 * 2 + 1][0] = r[2]; b[n2 * 2 + 1][1] = r[3];
        }
#pragma unroll
        for (int mf = 0; mf < 2; mf++)
#pragma unroll
            for (int nf = 0; nf < 8; nf++) mmah(acc[mf][nf], a[mf], b[nf]);
    }
}

// MN-major-B 1-pass chunk: A@0, B@10240 (32 rows x 272B), ldsm.trans.
// If SCALED, multiply A fragments by per-row g factors (ga=rows r, gb=rows r+8).
template <bool SCALED>
__device__ __forceinline__ void chunk1t(uint32_t sbase, uint32_t aOff, uint32_t bOff,
                                        float acc[2][8][4],
                                        const __half2* ga, const __half2* gb) {
#pragma unroll
    for (int ks = 0; ks < 2; ks++) {
        uint32_t a[2][4], b[8][2];
#pragma unroll
        for (int mf = 0; mf < 2; mf++) {
            ldsm4(sbase + aOff + mf * 1280 + ks * 32, a[mf]);
            if (SCALED) {
                __half2* ap = reinterpret_cast<__half2*>(a[mf]);
                ap[0] = __hmul2(ap[0], ga[mf]);
                ap[2] = __hmul2(ap[2], ga[mf]);
                ap[1] = __hmul2(ap[1], gb[mf]);
                ap[3] = __hmul2(ap[3], gb[mf]);
            }
        }
#pragma unroll
        for (int n2 = 0; n2 < 4; n2++) {
            uint32_t r[4];
            ldsm4t(sbase + 10240 + bOff + (uint32_t)(ks * 16 * 272 + n2 * 32), r);
            b[n2 * 2][0] = r[0]; b[n2 * 2][1] = r[1];
            b[n2 * 2 + 1][0] = r[2]; b[n2 * 2 + 1][1] = r[3];
        }
#pragma unroll
        for (int mf = 0; mf < 2; mf++)
#pragma unroll
            for (int nf = 0; nf < 8; nf++) mmah(acc[mf][nf], a[mf], b[nf]);
    }
}

struct __align__(8) hpair { __half2 a, b; };
__device__ __forceinline__ hpair to_h(float4 v) {
    hpair r; r.a = __floats2half2_rn(v.x, v.y); r.b = __floats2half2_rn(v.z, v.w); return r;
}

// ---------------- cvtw: W fp32 -> fp16 (SCALE folded into Wq) ----------------
__global__ void cvtw_kernel(const float* __restrict__ Wq, const float* __restrict__ Wk,
                            const float* __restrict__ Wv) {
    int i = (blockIdx.x * 256 + threadIdx.x) * 4;
    int z = i / 147456, r = i - z * 147456;
    const float* W = (z == 0) ? Wq : ((z == 1) ? Wk : Wv);
    float4 v = *(const float4*)(W + r);
    float s = (z == 0) ? SCALE : 1.f;
    v.x *= s; v.y *= s; v.z *= s; v.w *= s;
    *(hpair*)&g_Wh[i] = to_h(v);
}

// ---------------- proj: X fp32 (convert in stage) x W fp16, 3-stage pipeline ----------------
__global__ void __launch_bounds__(256, 2) proj_kernel(const float* __restrict__ X) {
    extern __shared__ char smem[];
    int tid = threadIdx.x, lane = tid & 31, wid = tid >> 5, wm = wid & 3, wn = wid >> 2;
    uint32_t sb = smem_u32(smem);
    int nt = blockIdx.x * 128, mt = blockIdx.y * 128, z = blockIdx.z;
    const float*  gA = X + (size_t)mt * 384;
    const __half* gW = g_Wh + (size_t)z * 147456 + nt;
    ACC_DECL();

    float4 va[4]; uint4 wb[2];
    auto ldg = [&](int c) {
#pragma unroll
        for (int i = 0; i < 4; i++) {
            int lin = tid + 256 * i, row = lin >> 3, c4 = (lin & 7) * 4;
            va[i] = *(const float4*)(gA + (size_t)row * 384 + c * 32 + c4);
        }
#pragma unroll
        for (int i = 0; i < 2; i++) {
            int lin = tid + 256 * i, r2 = lin >> 4, c2 = (lin & 15) * 8;
            wb[i] = *(const uint4*)(gW + (size_t)(c * 32 + r2) * 384 + c2);
        }
    };
    auto stg = [&](char* buf) {
#pragma unroll
        for (int i = 0; i < 4; i++) {
            int lin = tid + 256 * i, row = lin >> 3, c4 = (lin & 7) * 4;
            *(hpair*)(buf + row * 80 + c4 * 2) = to_h(va[i]);
        }
#pragma unroll
        for (int i = 0; i < 2; i++) {
            int lin = tid + 256 * i, r2 = lin >> 4, c2 = (lin & 15) * 8;
            *(uint4*)(buf + 10240 + r2 * 272 + c2 * 2) = wb[i];
        }
    };
    uint32_t aOff = AOFF(wm, lane), bOff = BOFFT(wn, lane);
    ldg(0); stg(smem); ldg(1);
    __syncthreads();
    int rs = 0;
    for (int c = 0; c < 12; c++) {
        int ws = (rs == 2) ? 0 : rs + 1;
        if (c + 1 < 12) stg(smem + ws * STG_T);
        if (c + 2 < 12) ldg(c + 2);
        chunk1t<false>(sb + (uint32_t)(rs * STG_T), aOff, bOff, acc, 0, 0);
        __syncthreads();
        rs = ws;
    }

    __half* Yh = (z == 0) ? g_Qh : ((z == 1) ? g_Kh : g_Vh);
#pragma unroll
    for (int mf = 0; mf < 2; mf++)
#pragma unroll
        for (int h = 0; h < 2; h++) {
            int row = mt + wm * 32 + mf * 16 + (lane >> 2) + h * 8;
#pragma unroll
            for (int nf = 0; nf < 8; nf++) {
                int col = nt + wn * 64 + nf * 8 + (lane & 3) * 2;
                *(__half2*)&Yh[(size_t)row * 384 + col] =
                    __floats2half2_rn(acc[mf][nf][h * 2], acc[mf][nf][h * 2 + 1]);
            }
        }
}

// ---------------- qk: 3-stage pipeline + barrier-free per-group softmax ----------------
__global__ void __launch_bounds__(256, 2) qk_kernel() {
    extern __shared__ char smem[];
    int tid = threadIdx.x, lane = tid & 31, wid = tid >> 5, wm = wid & 3, wn = wid >> 2;
    uint32_t sb = smem_u32(smem);
    int b = blockIdx.y, r_ = blockIdx.x, qt = 0;
    while (r_ > qt) { r_ -= qt + 1; qt++; }
    int kt = r_;
    size_t qb = ((size_t)b * 2048 + qt * 128) * 384;
    size_t kb = ((size_t)b * 2048 + kt * 128) * 384;
    ACC_DECL();

    uint4 rv[4];
    auto ldg = [&](int c) {
#pragma unroll
        for (int i = 0; i < 2; i++) {
            int lin = tid + 256 * i, rr = lin >> 2, cc = (lin & 3) * 8;
            size_t o = (size_t)rr * 384 + c * 32 + cc;
            rv[i * 2 + 0] = *(const uint4*)(g_Qh + qb + o);
            rv[i * 2 + 1] = *(const uint4*)(g_Kh + kb + o);
        }
    };
    auto stg = [&](char* buf) {
#pragma unroll
        for (int i = 0; i < 2; i++) {
            int lin = tid + 256 * i, rr = lin >> 2, cc = (lin & 3) * 8;
            int o = rr * 80 + cc * 2;
            *(uint4*)(buf + o)         = rv[i * 2 + 0];
            *(uint4*)(buf + 10240 + o) = rv[i * 2 + 1];
        }
    };
    uint32_t aOff = AOFF(wm, lane), bOff = BOFF(wn, lane);
    ldg(0); stg(smem); ldg(1);
    __syncthreads();
    int rs = 0;
    for (int c = 0; c < 12; c++) {
        int ws = (rs == 2) ? 0 : rs + 1;
        if (c + 1 < 12) stg(smem + ws * STG_QK);
        if (c + 2 < 12) ldg(c + 2);
        chunk1(sb + (uint32_t)(rs * STG_QK), aOff, bOff, acc);
        __syncthreads();
        rs = ws;
    }

    // ---- barrier-free epilogue: mask, per-64col-group max/exp/sum, P~ store ----
    float pm[2][2] = {{-1e30f, -1e30f}, {-1e30f, -1e30f}};
#pragma unroll
    for (int mf = 0; mf < 2; mf++)
#pragma unroll
        for (int nf = 0; nf < 8; nf++)
#pragma unroll
            for (int q = 0; q < 4; q++) {
                int h = q >> 1;
                int qg = qt * 128 + wm * 32 + mf * 16 + (lane >> 2) + h * 8;
                int kg = kt * 128 + wn * 64 + nf * 8 + (lane & 3) * 2 + (q & 1);
                if (kg > qg) acc[mf][nf][q] = -1e30f;
                pm[mf][h] = fmaxf(pm[mf][h], acc[mf][nf][q]);
            }
#pragma unroll
    for (int mf = 0; mf < 2; mf++)
#pragma unroll
        for (int h = 0; h < 2; h++) {
            pm[mf][h] = fmaxf(pm[mf][h], __shfl_xor_sync(~0u, pm[mf][h], 1));
            pm[mf][h] = fmaxf(pm[mf][h], __shfl_xor_sync(~0u, pm[mf][h], 2));
        }
    float ps[2][2] = {{0.f, 0.f}, {0.f, 0.f}};
#pragma unroll
    for (int mf = 0; mf < 2; mf++)
#pragma unroll
        for (int nf = 0; nf < 8; nf++)
#pragma unroll
            for (int q = 0; q < 4; q++) {
                int h = q >> 1;
                float p = __expf(acc[mf][nf][q] - pm[mf][h]);
                acc[mf][nf][q] = p;
                ps[mf][h] += p;
            }
#pragma unroll
    for (int mf = 0; mf < 2; mf++)
#pragma unroll
        for (int h = 0; h < 2; h++) {
            ps[mf][h] += __shfl_xor_sync(~0u, ps[mf][h], 1);
            ps[mf][h] += __shfl_xor_sync(~0u, ps[mf][h], 2);
        }
    // stats: [b][group][qrow], group = kt*2 + wn (64 key-cols per group)
    size_t statb = ((size_t)b * 32 + kt * 2 + wn) * 2048 + qt * 128;
    if ((lane & 3) == 0)
#pragma unroll
        for (int mf = 0; mf < 2; mf++)
#pragma unroll
            for (int h = 0; h < 2; h++) {
                int rl = wm * 32 + mf * 16 + (lane >> 2) + h * 8;
                g_mt[statb + rl] = pm[mf][h];
                g_lt[statb + rl] = ps[mf][h];
            }
    __half* Prow = g_Pt + ((size_t)b * 2048 + qt * 128) * 2048 + (size_t)kt * 128;
#pragma unroll
    for (int mf = 0; mf < 2; mf++)
#pragma unroll
        for (int h = 0; h < 2; h++) {
            int rl = wm * 32 + mf * 16 + (lane >> 2) + h * 8;
#pragma unroll
            for (int nf = 0; nf < 8; nf++) {
                int col = wn * 64 + nf * 8 + (lane & 3) * 2;
                *(__half2*)&Prow[(size_t)rl * 2048 + col] =
                    __floats2half2_rn(acc[mf][nf][h * 2], acc[mf][nf][h * 2 + 1]);
            }
        }
}

// ---------------- pv: 3-stage pipeline; fused norm (per-group g); g on A fragments ----------------
__global__ void __launch_bounds__(256, 2) pv_kernel(float* __restrict__ out) {
    extern __shared__ char smem[];
    int tid = threadIdx.x, lane = tid & 31, wid = tid >> 5, wm = wid & 3, wn = wid >> 2;
    uint32_t sb = smem_u32(smem);
    int nt = blockIdx.x * 128, qt = 15 - (int)blockIdx.y, b = blockIdx.z;
    int nch = (qt + 1) * 4;              // 32-key chunks
    int ngrp = (qt + 1) * 2;             // 64-key stat groups
    const __half* Pb = g_Pt + ((size_t)b * 2048 + qt * 128) * 2048;
    const __half* Vh = g_Vh + (size_t)b * 2048 * 384 + nt;
    float* sg = (float*)(smem + SMEM_T3);        // [32 groups][128 rows]
    ACC_DECL();

    uint4 rv[4];
    auto ldg = [&](int c) {
#pragma unroll
        for (int i = 0; i < 2; i++) {
            int lin = tid + 256 * i;
            int rr = lin >> 2, cc = (lin & 3) * 8;            // A: 128 x 32
            rv[i * 2 + 0] = *(const uint4*)(Pb + (size_t)rr * 2048 + c * 32 + cc);
            int r2 = lin >> 4, c2 = (lin & 15) * 8;           // B: 32 x 128
            rv[i * 2 + 1] = *(const uint4*)(Vh + (size_t)(c * 32 + r2) * 384 + c2);
        }
    };
    auto stg = [&](char* buf) {
#pragma unroll
        for (int i = 0; i < 2; i++) {
            int lin = tid + 256 * i;
            int rr = lin >> 2, cc = (lin & 3) * 8;
            *(uint4*)(buf + rr * 80 + cc * 2) = rv[i * 2 + 0];
            int r2 = lin >> 4, c2 = (lin & 15) * 8;
            *(uint4*)(buf + 10240 + r2 * 272 + c2 * 2) = rv[i * 2 + 1];
        }
    };
    uint32_t aOff = AOFF(wm, lane), bOff = BOFFT(wn, lane);
    ldg(0);
    // fused norm: per-row fold factors for all groups (overlaps ldg latency)
    if (tid < 128) {
        size_t base = ((size_t)b * 32) * 2048 + qt * 128 + tid;
        float m = -1e30f;
        for (int t = 0; t < ngrp; t++) m = fmaxf(m, g_mt[base + (size_t)t * 2048]);
        float l = 0.f;
        for (int t = 0; t < ngrp; t++)
            l += __expf(g_mt[base + (size_t)t * 2048] - m) * g_lt[base + (size_t)t * 2048];
        float inv = 1.f / l;
        for (int t = 0; t < ngrp; t++)
            sg[t * 128 + tid] = __expf(g_mt[base + (size_t)t * 2048] - m) * inv;
    }
    stg(smem); ldg(1);
    __syncthreads();

    int rbase = wm * 32 + (lane >> 2);
    int rs = 0;
    for (int c = 0; c < nch; c++) {
        __half2 ga[2], gb[2];
        const float* gp = sg + (c >> 1) * 128;
#pragma unroll
        for (int mf = 0; mf < 2; mf++) {
            ga[mf] = __float2half2_rn(gp[rbase + mf * 16]);
            gb[mf] = __float2half2_rn(gp[rbase + mf * 16 + 8]);
        }
        int ws = (rs == 2) ? 0 : rs + 1;
        if (c + 1 < nch) stg(smem + ws * STG_T);
        if (c + 2 < nch) ldg(c + 2);
        chunk1t<true>(sb + (uint32_t)(rs * STG_T), aOff, bOff, acc, ga, gb);
        __syncthreads();
        rs = ws;
    }

    float* Y = out + ((size_t)b * 2048 + qt * 128) * 384 + nt;
#pragma unroll
    for (int mf = 0; mf < 2; mf++)
#pragma unroll
        for (int h = 0; h < 2; h++) {
            int row = wm * 32 + mf * 16 + (lane >> 2) + h * 8;
#pragma unroll
            for (int nf = 0; nf < 8; nf++) {
                float2 v = make_float2(acc[mf][nf][h * 2], acc[mf][nf][h * 2 + 1]);
                *(float2*)&Y[(size_t)row * 384 + wn * 64 + nf * 8 + (lane & 3) * 2] = v;
            }
        }
}

extern "C" void kernel_launch(void* const* d_in, const int* in_sizes, int n_in,
                              void* d_out, int out_size) {
    const float* x  = (const float*)d_in[0];
    const float* Wq = (const float*)d_in[1];
    const float* Wk = (const float*)d_in[2];
    const float* Wv = (const float*)d_in[3];
    float* out = (float*)d_out;
    (void)in_sizes; (void)n_in; (void)out_size;

    cudaFuncSetAttribute(proj_kernel, cudaFuncAttributeMaxDynamicSharedMemorySize, SMEM_T3);
    cudaFuncSetAttribute(qk_kernel,   cudaFuncAttributeMaxDynamicSharedMemorySize, SMEM_QK3);
    cudaFuncSetAttribute(pv_kernel,   cudaFuncAttributeMaxDynamicSharedMemorySize, SMEM_PV3);

    cvtw_kernel<<<432, 256>>>(Wq, Wk, Wv);
    proj_kernel<<<dim3(3, 256, 3), 256, SMEM_T3>>>(x);
    qk_kernel<<<dim3(136, 16), 256, SMEM_QK3>>>();
    pv_kernel<<<dim3(3, 16, 16), 256, SMEM_PV3>>>(out);
}

// round 14
// speedup vs baseline: 1.0993x; 1.0022x over previous
#include <cuda_runtime.h>
#include <cuda_fp16.h>
#include <cstdint>

#define SCALE 0.05103103630798288f   // 384^-0.5
#define STG_QK 20480                  // A 10240 + B 10240 (K-major)
#define STG_T  18944                  // A 10240 + B 8704  (MN-major B)
#define SMEM_QK3 (3 * STG_QK)         // 61440
#define SMEM_T3  (3 * STG_T)          // 56832
#define SMEM_PV3 (SMEM_T3 + 16384)    // + sg[32 groups][128 rows] fp32

__device__ __half g_Wh[3 * 384 * 384];           // W[k][n] fp16, Wq pre-scaled
__device__ __half g_Qh[16 * 2048 * 384];
__device__ __half g_Kh[16 * 2048 * 384];
__device__ __half g_Vh[16 * 2048 * 384];
__device__ __half g_Pt[16ll * 2048 * 2048];      // P~ = exp(S - m_grp), fp16
__device__ float  g_mt[16 * 32 * 2048];          // [b][group(64 keys)][qrow]
__device__ float  g_lt[16 * 32 * 2048];
__device__ float  g_g [16 * 32 * 2048];          // fold factor exp(m_t-M)/l

__device__ __forceinline__ uint32_t smem_u32(const void* p) {
    uint32_t a;
    asm("{ .reg .u64 t; cvta.to.shared.u64 t, %1; cvt.u32.u64 %0, t; }" : "=r"(a) : "l"(p));
    return a;
}
__device__ __forceinline__ void ldsm4(uint32_t addr, uint32_t* r) {
    asm volatile("ldmatrix.sync.aligned.m8n8.x4.shared.b16 {%0,%1,%2,%3}, [%4];"
        : "=r"(r[0]), "=r"(r[1]), "=r"(r[2]), "=r"(r[3]) : "r"(addr));
}
__device__ __forceinline__ void ldsm4t(uint32_t addr, uint32_t* r) {
    asm volatile("ldmatrix.sync.aligned.m8n8.x4.trans.shared.b16 {%0,%1,%2,%3}, [%4];"
        : "=r"(r[0]), "=r"(r[1]), "=r"(r[2]), "=r"(r[3]) : "r"(addr));
}
__device__ __forceinline__ void mmah(float* c, const uint32_t* a, const uint32_t* b) {
    asm volatile("mma.sync.aligned.m16n8k16.row.col.f32.f16.f16.f32 "
        "{%0,%1,%2,%3}, {%4,%5,%6,%7}, {%8,%9}, {%0,%1,%2,%3};"
        : "+f"(c[0]), "+f"(c[1]), "+f"(c[2]), "+f"(c[3])
        : "r"(a[0]), "r"(a[1]), "r"(a[2]), "r"(a[3]), "r"(b[0]), "r"(b[1]));
}

#define ACC_DECL()                                   \
    float acc[2][8][4];                              \
    _Pragma("unroll") for (int i_ = 0; i_ < 2; i_++) \
    _Pragma("unroll") for (int j_ = 0; j_ < 8; j_++) \
    _Pragma("unroll") for (int q_ = 0; q_ < 4; q_++) acc[i_][j_][q_] = 0.f;

#define AOFF(wm, lane) ((uint32_t)(((wm) * 32 + ((lane) & 15)) * 80 + ((lane) >> 4) * 16))
#define BOFF(wn, lane) ((uint32_t)(((wn) * 64 + (((lane) >> 4) & 1) * 8 + ((lane) & 7)) * 80 + \
                                   (((lane) >> 3) & 1) * 16))
#define BOFFT(wn, lane) ((uint32_t)(((((lane) >> 3) & 1) * 8 + ((lane) & 7)) * 272 + \
                                    ((wn) * 64 + (((lane) >> 4) & 1) * 8) * 2))

// K-major 1-pass chunk: A@0 (80B stride), B@10240 (80B stride)
__device__ __forceinline__ void chunk1(uint32_t sbase, uint32_t aOff, uint32_t bOff,
                                       float acc[2][8][4]) {
#pragma unroll
    for (int ks = 0; ks < 2; ks++) {
        uint32_t a[2][4], b[8][2];
#pragma unroll
        for (int mf = 0; mf < 2; mf++) ldsm4(sbase + aOff + mf * 1280 + ks * 32, a[mf]);
#pragma unroll
        for (int n2 = 0; n2 < 4; n2++) {
            uint32_t r[4];
            ldsm4(sbase + 10240 + bOff + n2 * 1280 + ks * 32, r);
            b[n2 * 2][0] = r[0]; b[n2 * 2][1] = r[1];
            b[n2 * 2 + 1][0] = r[2]; b[n2 * 2 + 1][1] = r[3];
        }
#pragma unroll
        for (int mf = 0; mf < 2; mf++)
#pragma unroll
            for (int nf = 0; nf < 8; nf++) mmah(acc[mf][nf], a[mf], b[nf]);
    }
}

// MN-major-B 1-pass chunk: A@0, B@10240 (32 rows x 272B), ldsm.trans.
// If SCALED, multiply A fragments by per-row g factors (ga=rows r, gb=rows r+8).
template <bool SCALED>
__device__ __forceinline__ void chunk1t(uint32_t sbase, uint32_t aOff, uint32_t bOff,
                                        float acc[2][8][4],
                                        const __half2* ga, const __half2* gb) {
#pragma unroll
    for (int ks = 0; ks < 2; ks++) {
        uint32_t a[2][4], b[8][2];
#pragma unroll
        for (int mf = 0; mf < 2; mf++) {
            ldsm4(sbase + aOff + mf * 1280 + ks * 32, a[mf]);
            if (SCALED) {
                __half2* ap = reinterpret_cast<__half2*>(a[mf]);
                ap[0] = __hmul2(ap[0], ga[mf]);
                ap[2] = __hmul2(ap[2], ga[mf]);
                ap[1] = __hmul2(ap[1], gb[mf]);
                ap[3] = __hmul2(ap[3], gb[mf]);
            }
        }
#pragma unroll
        for (int n2 = 0; n2 < 4; n2++) {
            uint32_t r[4];
            ldsm4t(sbase + 10240 + bOff + (uint32_t)(ks * 16 * 272 + n2 * 32), r);
            b[n2 * 2][0] = r[0]; b[n2 * 2][1] = r[1];
            b[n2 * 2 + 1][0] = r[2]; b[n2 * 2 + 1][1] = r[3];
        }
#pragma unroll
        for (int mf = 0; mf < 2; mf++)
#pragma unroll
            for (int nf = 0; nf < 8; nf++) mmah(acc[mf][nf], a[mf], b[nf]);
    }
}

struct __align__(8) hpair { __half2 a, b; };
__device__ __forceinline__ hpair to_h(float4 v) {
    hpair r; r.a = __floats2half2_rn(v.x, v.y); r.b = __floats2half2_rn(v.z, v.w); return r;
}

// ---------------- cvtw: W fp32 -> fp16 (SCALE folded into Wq) ----------------
__global__ void cvtw_kernel(const float* __restrict__ Wq, const float* __restrict__ Wk,
                            const float* __restrict__ Wv) {
    int i = (blockIdx.x * 256 + threadIdx.x) * 4;
    int z = i / 147456, r = i - z * 147456;
    const float* W = (z == 0) ? Wq : ((z == 1) ? Wk : Wv);
    float4 v = *(const float4*)(W + r);
    float s = (z == 0) ? SCALE : 1.f;
    v.x *= s; v.y *= s; v.z *= s; v.w *= s;
    *(hpair*)&g_Wh[i] = to_h(v);
}

// ---------------- proj: X fp32 (convert in stage) x W fp16, 3-stage pipeline ----------------
__global__ void __launch_bounds__(256, 2) proj_kernel(const float* __restrict__ X) {
    extern __shared__ char smem[];
    int tid = threadIdx.x, lane = tid & 31, wid = tid >> 5, wm = wid & 3, wn = wid >> 2;
    uint32_t sb = smem_u32(smem);
    int nt = blockIdx.x * 128, mt = blockIdx.y * 128, z = blockIdx.z;
    const float*  gA = X + (size_t)mt * 384;
    const __half* gW = g_Wh + (size_t)z * 147456 + nt;
    ACC_DECL();

    float4 va[4]; uint4 wb[2];
    auto ldg = [&](int c) {
#pragma unroll
        for (int i = 0; i < 4; i++) {
            int lin = tid + 256 * i, row = lin >> 3, c4 = (lin & 7) * 4;
            va[i] = *(const float4*)(gA + (size_t)row * 384 + c * 32 + c4);
        }
#pragma unroll
        for (int i = 0; i < 2; i++) {
            int lin = tid + 256 * i, r2 = lin >> 4, c2 = (lin & 15) * 8;
            wb[i] = *(const uint4*)(gW + (size_t)(c * 32 + r2) * 384 + c2);
        }
    };
    auto stg = [&](char* buf) {
#pragma unroll
        for (int i = 0; i < 4; i++) {
            int lin = tid + 256 * i, row = lin >> 3, c4 = (lin & 7) * 4;
            *(hpair*)(buf + row * 80 + c4 * 2) = to_h(va[i]);
        }
#pragma unroll
        for (int i = 0; i < 2; i++) {
            int lin = tid + 256 * i, r2 = lin >> 4, c2 = (lin & 15) * 8;
            *(uint4*)(buf + 10240 + r2 * 272 + c2 * 2) = wb[i];
        }
    };
    uint32_t aOff = AOFF(wm, lane), bOff = BOFFT(wn, lane);
    ldg(0); stg(smem); ldg(1);
    __syncthreads();
    int rs = 0;
    for (int c = 0; c < 12; c++) {
        int ws = (rs == 2) ? 0 : rs + 1;
        if (c + 1 < 12) stg(smem + ws * STG_T);
        if (c + 2 < 12) ldg(c + 2);
        chunk1t<false>(sb + (uint32_t)(rs * STG_T), aOff, bOff, acc, 0, 0);
        __syncthreads();
        rs = ws;
    }

    __half* Yh = (z == 0) ? g_Qh : ((z == 1) ? g_Kh : g_Vh);
#pragma unroll
    for (int mf = 0; mf < 2; mf++)
#pragma unroll
        for (int h = 0; h < 2; h++) {
            int row = mt + wm * 32 + mf * 16 + (lane >> 2) + h * 8;
#pragma unroll
            for (int nf = 0; nf < 8; nf++) {
                int col = nt + wn * 64 + nf * 8 + (lane & 3) * 2;
                *(__half2*)&Yh[(size_t)row * 384 + col] =
                    __floats2half2_rn(acc[mf][nf][h * 2], acc[mf][nf][h * 2 + 1]);
            }
        }
}

// ---------------- qk: 3-stage pipeline + barrier-free per-group softmax ----------------
__global__ void __launch_bounds__(256, 2) qk_kernel() {
    extern __shared__ char smem[];
    int tid = threadIdx.x, lane = tid & 31, wid = tid >> 5, wm = wid & 3, wn = wid >> 2;
    uint32_t sb = smem_u32(smem);
    int b = blockIdx.y, r_ = blockIdx.x, qt = 0;
    while (r_ > qt) { r_ -= qt + 1; qt++; }
    int kt = r_;
    size_t qb = ((size_t)b * 2048 + qt * 128) * 384;
    size_t kb = ((size_t)b * 2048 + kt * 128) * 384;
    ACC_DECL();

    uint4 rv[4];
    auto ldg = [&](int c) {
#pragma unroll
        for (int i = 0; i < 2; i++) {
            int lin = tid + 256 * i, rr = lin >> 2, cc = (lin & 3) * 8;
            size_t o = (size_t)rr * 384 + c * 32 + cc;
            rv[i * 2 + 0] = *(const uint4*)(g_Qh + qb + o);
            rv[i * 2 + 1] = *(const uint4*)(g_Kh + kb + o);
        }
    };
    auto stg = [&](char* buf) {
#pragma unroll
        for (int i = 0; i < 2; i++) {
            int lin = tid + 256 * i, rr = lin >> 2, cc = (lin & 3) * 8;
            int o = rr * 80 + cc * 2;
            *(uint4*)(buf + o)         = rv[i * 2 + 0];
            *(uint4*)(buf + 10240 + o) = rv[i * 2 + 1];
        }
    };
    uint32_t aOff = AOFF(wm, lane), bOff = BOFF(wn, lane);
    ldg(0); stg(smem); ldg(1);
    __syncthreads();
    int rs = 0;
    for (int c = 0; c < 12; c++) {
        int ws = (rs == 2) ? 0 : rs + 1;
        if (c + 1 < 12) stg(smem + ws * STG_QK);
        if (c + 2 < 12) ldg(c + 2);
        chunk1(sb + (uint32_t)(rs * STG_QK), aOff, bOff, acc);
        __syncthreads();
        rs = ws;
    }

    // ---- barrier-free epilogue: mask, per-64col-group max/exp/sum, P~ store ----
    float pm[2][2] = {{-1e30f, -1e30f}, {-1e30f, -1e30f}};
#pragma unroll
    for (int mf = 0; mf < 2; mf++)
#pragma unroll
        for (int nf = 0; nf < 8; nf++)
#pragma unroll
            for (int q = 0; q < 4; q++) {
                int h = q >> 1;
                int qg = qt * 128 + wm * 32 + mf * 16 + (lane >> 2) + h * 8;
                int kg = kt * 128 + wn * 64 + nf * 8 + (lane & 3) * 2 + (q & 1);
                if (kg > qg) acc[mf][nf][q] = -1e30f;
                pm[mf][h] = fmaxf(pm[mf][h], acc[mf][nf][q]);
            }
#pragma unroll
    for (int mf = 0; mf < 2; mf++)
#pragma unroll
        for (int h = 0; h < 2; h++) {
            pm[mf][h] = fmaxf(pm[mf][h], __shfl_xor_sync(~0u, pm[mf][h], 1));
            pm[mf][h] = fmaxf(pm[mf][h], __shfl_xor_sync(~0u, pm[mf][h], 2));
        }
    float ps[2][2] = {{0.f, 0.f}, {0.f, 0.f}};
#pragma unroll
    for (int mf = 0; mf < 2; mf++)
#pragma unroll
        for (int nf = 0; nf < 8; nf++)
#pragma unroll
            for (int q = 0; q < 4; q++) {
                int h = q >> 1;
                float p = __expf(acc[mf][nf][q] - pm[mf][h]);
                acc[mf][nf][q] = p;
                ps[mf][h] += p;
            }
#pragma unroll
    for (int mf = 0; mf < 2; mf++)
#pragma unroll
        for (int h = 0; h < 2; h++) {
            ps[mf][h] += __shfl_xor_sync(~0u, ps[mf][h], 1);
            ps[mf][h] += __shfl_xor_sync(~0u, ps[mf][h], 2);
        }
    // stats: [b][group][qrow], group = kt*2 + wn (64 key-cols per group)
    size_t statb = ((size_t)b * 32 + kt * 2 + wn) * 2048 + qt * 128;
    if ((lane & 3) == 0)
#pragma unroll
        for (int mf = 0; mf < 2; mf++)
#pragma unroll
            for (int h = 0; h < 2; h++) {
                int rl = wm * 32 + mf * 16 + (lane >> 2) + h * 8;
                g_mt[statb + rl] = pm[mf][h];
                g_lt[statb + rl] = ps[mf][h];
            }
    __half* Prow = g_Pt + ((size_t)b * 2048 + qt * 128) * 2048 + (size_t)kt * 128;
#pragma unroll
    for (int mf = 0; mf < 2; mf++)
#pragma unroll
        for (int h = 0; h < 2; h++) {
            int rl = wm * 32 + mf * 16 + (lane >> 2) + h * 8;
#pragma unroll
            for (int nf = 0; nf < 8; nf++) {
                int col = wn * 64 + nf * 8 + (lane & 3) * 2;
                *(__half2*)&Prow[(size_t)rl * 2048 + col] =
                    __floats2half2_rn(acc[mf][nf][h * 2], acc[mf][nf][h * 2 + 1]);
            }
        }
}

// ---------------- norm: parallel fold of M, 1/l into per-group row factors ----------------
__global__ void __launch_bounds__(128) norm_kernel() {
    int bq = blockIdx.x;                 // b*16 + qt
    int b = bq >> 4, qt = bq & 15, row = threadIdx.x;
    int ngrp = (qt + 1) * 2;
    size_t base = ((size_t)b * 32) * 2048 + qt * 128 + row;
    float m = -1e30f;
    for (int t = 0; t < ngrp; t++) m = fmaxf(m, g_mt[base + (size_t)t * 2048]);
    float l = 0.f;
    for (int t = 0; t < ngrp; t++)
        l += __expf(g_mt[base + (size_t)t * 2048] - m) * g_lt[base + (size_t)t * 2048];
    float inv = 1.f / l;
    for (int t = 0; t < ngrp; t++)
        g_g[base + (size_t)t * 2048] = __expf(g_mt[base + (size_t)t * 2048] - m) * inv;
}

// ---------------- pv: 3-stage pipeline; sg bulk-loaded; g on A fragments ----------------
__global__ void __launch_bounds__(256, 2) pv_kernel(float* __restrict__ out) {
    extern __shared__ char smem[];
    int tid = threadIdx.x, lane = tid & 31, wid = tid >> 5, wm = wid & 3, wn = wid >> 2;
    uint32_t sb = smem_u32(smem);
    int nt = blockIdx.x * 128, qt = 15 - (int)blockIdx.y, b = blockIdx.z;
    int nch = (qt + 1) * 4;              // 32-key chunks
    int ngrp = (qt + 1) * 2;             // 64-key stat groups
    const __half* Pb = g_Pt + ((size_t)b * 2048 + qt * 128) * 2048;
    const __half* Vh = g_Vh + (size_t)b * 2048 * 384 + nt;
    float* sg = (float*)(smem + SMEM_T3);        // [32 groups][128 rows]
    ACC_DECL();

    uint4 rv[4];
    auto ldg = [&](int c) {
#pragma unroll
        for (int i = 0; i < 2; i++) {
            int lin = tid + 256 * i;
            int rr = lin >> 2, cc = (lin & 3) * 8;            // A: 128 x 32
            rv[i * 2 + 0] = *(const uint4*)(Pb + (size_t)rr * 2048 + c * 32 + cc);
            int r2 = lin >> 4, c2 = (lin & 15) * 8;           // B: 32 x 128
            rv[i * 2 + 1] = *(const uint4*)(Vh + (size_t)(c * 32 + r2) * 384 + c2);
        }
    };
    auto stg = [&](char* buf) {
#pragma unroll
        for (int i = 0; i < 2; i++) {
            int lin = tid + 256 * i;
            int rr = lin >> 2, cc = (lin & 3) * 8;
            *(uint4*)(buf + rr * 80 + cc * 2) = rv[i * 2 + 0];
            int r2 = lin >> 4, c2 = (lin & 15) * 8;
            *(uint4*)(buf + 10240 + r2 * 272 + c2 * 2) = rv[i * 2 + 1];
        }
    };
    uint32_t aOff = AOFF(wm, lane), bOff = BOFFT(wn, lane);
    ldg(0);
    // bulk-load precomputed fold factors (coalesced, parallel)
    {
        size_t gbase = ((size_t)b * 32) * 2048 + qt * 128;
        for (int i = tid; i < ngrp * 128; i += 256)
            sg[i] = g_g[gbase + (size_t)(i >> 7) * 2048 + (i & 127)];
    }
    stg(smem); ldg(1);
    __syncthreads();

    int rbase = wm * 32 + (lane >> 2);
    int rs = 0;
    __half2 ga[2], gb[2];
    for (int c = 0; c < nch; c++) {
        if ((c & 1) == 0) {
            const float* gp = sg + (c >> 1) * 128;
#pragma unroll
            for (int mf = 0; mf < 2; mf++) {
                ga[mf] = __float2half2_rn(gp[rbase + mf * 16]);
                gb[mf] = __float2half2_rn(gp[rbase + mf * 16 + 8]);
            }
        }
        int ws = (rs == 2) ? 0 : rs + 1;
        if (c + 1 < nch) stg(smem + ws * STG_T);
        if (c + 2 < nch) ldg(c + 2);
        chunk1t<true>(sb + (uint32_t)(rs * STG_T), aOff, bOff, acc, ga, gb);
        __syncthreads();
        rs = ws;
    }

    float* Y = out + ((size_t)b * 2048 + qt * 128) * 384 + nt;
#pragma unroll
    for (int mf = 0; mf < 2; mf++)
#pragma unroll
        for (int h = 0; h < 2; h++) {
            int row = wm * 32 + mf * 16 + (lane >> 2) + h * 8;
#pragma unroll
            for (int nf = 0; nf < 8; nf++) {
                float2 v = make_float2(acc[mf][nf][h * 2], acc[mf][nf][h * 2 + 1]);
                *(float2*)&Y[(size_t)row * 384 + wn * 64 + nf * 8 + (lane & 3) * 2] = v;
            }
        }
}

extern "C" void kernel_launch(void* const* d_in, const int* in_sizes, int n_in,
                              void* d_out, int out_size) {
    const float* x  = (const float*)d_in[0];
    const float* Wq = (const float*)d_in[1];
    const float* Wk = (const float*)d_in[2];
    const float* Wv = (const float*)d_in[3];
    float* out = (float*)d_out;
    (void)in_sizes; (void)n_in; (void)out_size;

    cudaFuncSetAttribute(proj_kernel, cudaFuncAttributeMaxDynamicSharedMemorySize, SMEM_T3);
    cudaFuncSetAttribute(qk_kernel,   cudaFuncAttributeMaxDynamicSharedMemorySize, SMEM_QK3);
    cudaFuncSetAttribute(pv_kernel,   cudaFuncAttributeMaxDynamicSharedMemorySize, SMEM_PV3);

    cvtw_kernel<<<432, 256>>>(Wq, Wk, Wv);
    proj_kernel<<<dim3(3, 256, 3), 256, SMEM_T3>>>(x);
    qk_kernel<<<dim3(136, 16), 256, SMEM_QK3>>>();
    norm_kernel<<<256, 128>>>();
    pv_kernel<<<dim3(3, 16, 16), 256, SMEM_PV3>>>(out);
}

// round 15
// speedup vs baseline: 1.1975x; 1.0894x over previous
#include <cuda_runtime.h>
#include <cuda_fp16.h>
#include <cstdint>

#define SCALE 0.05103103630798288f   // 384^-0.5
#define STG_QK 20480                  // A 10240 + B 10240 (K-major)
#define STG_T  18944                  // A 10240 + B 8704  (MN-major B)
#define SMEM_QK3 (3 * STG_QK)         // 61440
#define SMEM_T3  (3 * STG_T)          // 56832
#define SMEM_PV3 (SMEM_T3 + 8192)     // + sg[16 tiles][128 rows] fp32

__device__ __half g_Wh[3 * 384 * 384];           // W[k][n] fp16, Wq pre-scaled
__device__ __half g_Qh[16 * 2048 * 384];
__device__ __half g_Kh[16 * 2048 * 384];
__device__ __half g_Vh[16 * 2048 * 384];
__device__ __half g_Pt[16ll * 2048 * 2048];      // P~ = exp(S - m_tile), fp16
__device__ float  g_mt[16 * 16 * 16 * 128];      // [b][qt][kt][row] tile max
__device__ float  g_lt[16 * 16 * 16 * 128];      // per-tile row sum
__device__ float  g_g [16 * 16 * 16 * 128];      // fold factor exp(m_t-M)/l

__device__ __forceinline__ uint32_t smem_u32(const void* p) {
    uint32_t a;
    asm("{ .reg .u64 t; cvta.to.shared.u64 t, %1; cvt.u32.u64 %0, t; }" : "=r"(a) : "l"(p));
    return a;
}
__device__ __forceinline__ void ldsm4(uint32_t addr, uint32_t* r) {
    asm volatile("ldmatrix.sync.aligned.m8n8.x4.shared.b16 {%0,%1,%2,%3}, [%4];"
        : "=r"(r[0]), "=r"(r[1]), "=r"(r[2]), "=r"(r[3]) : "r"(addr));
}
__device__ __forceinline__ void ldsm4t(uint32_t addr, uint32_t* r) {
    asm volatile("ldmatrix.sync.aligned.m8n8.x4.trans.shared.b16 {%0,%1,%2,%3}, [%4];"
        : "=r"(r[0]), "=r"(r[1]), "=r"(r[2]), "=r"(r[3]) : "r"(addr));
}
__device__ __forceinline__ void mmah(float* c, const uint32_t* a, const uint32_t* b) {
    asm volatile("mma.sync.aligned.m16n8k16.row.col.f32.f16.f16.f32 "
        "{%0,%1,%2,%3}, {%4,%5,%6,%7}, {%8,%9}, {%0,%1,%2,%3};"
        : "+f"(c[0]), "+f"(c[1]), "+f"(c[2]), "+f"(c[3])
        : "r"(a[0]), "r"(a[1]), "r"(a[2]), "r"(a[3]), "r"(b[0]), "r"(b[1]));
}
// L2-only loads (no L1 allocation) for mainloop streams
__device__ __forceinline__ uint4 ldcg4(const void* p) {
    uint4 v;
    asm volatile("ld.global.cg.v4.u32 {%0,%1,%2,%3}, [%4];"
        : "=r"(v.x), "=r"(v.y), "=r"(v.z), "=r"(v.w) : "l"(p));
    return v;
}
__device__ __forceinline__ float4 ldcg4f(const void* p) {
    float4 v;
    asm volatile("ld.global.cg.v4.f32 {%0,%1,%2,%3}, [%4];"
        : "=f"(v.x), "=f"(v.y), "=f"(v.z), "=f"(v.w) : "l"(p));
    return v;
}

#define ACC_DECL()                                   \
    float acc[2][8][4];                              \
    _Pragma("unroll") for (int i_ = 0; i_ < 2; i_++) \
    _Pragma("unroll") for (int j_ = 0; j_ < 8; j_++) \
    _Pragma("unroll") for (int q_ = 0; q_ < 4; q_++) acc[i_][j_][q_] = 0.f;

#define AOFF(wm, lane) ((uint32_t)(((wm) * 32 + ((lane) & 15)) * 80 + ((lane) >> 4) * 16))
#define BOFF(wn, lane) ((uint32_t)(((wn) * 64 + (((lane) >> 4) & 1) * 8 + ((lane) & 7)) * 80 + \
                                   (((lane) >> 3) & 1) * 16))
#define BOFFT(wn, lane) ((uint32_t)(((((lane) >> 3) & 1) * 8 + ((lane) & 7)) * 272 + \
                                    ((wn) * 64 + (((lane) >> 4) & 1) * 8) * 2))

// K-major 1-pass chunk: A@0 (80B stride), B@10240 (80B stride)
__device__ __forceinline__ void chunk1(uint32_t sbase, uint32_t aOff, uint32_t bOff,
                                       float acc[2][8][4]) {
#pragma unroll
    for (int ks = 0; ks < 2; ks++) {
        uint32_t a[2][4], b[8][2];
#pragma unroll
        for (int mf = 0; mf < 2; mf++) ldsm4(sbase + aOff + mf * 1280 + ks * 32, a[mf]);
#pragma unroll
        for (int n2 = 0; n2 < 4; n2++) {
            uint32_t r[4];
            ldsm4(sbase + 10240 + bOff + n2 * 1280 + ks * 32, r);
            b[n2 * 2][0] = r[0]; b[n2 * 2][1] = r[1];
            b[n2 * 2 + 1][0] = r[2]; b[n2 * 2 + 1][1] = r[3];
        }
#pragma unroll
        for (int mf = 0; mf < 2; mf++)
#pragma unroll
            for (int nf = 0; nf < 8; nf++) mmah(acc[mf][nf], a[mf], b[nf]);
    }
}

// MN-major-B 1-pass chunk: A@0, B@10240 (32 rows x 272B), ldsm.trans.
// If SCALED, multiply A fragments by per-row g factors (ga=rows r, gb=rows r+8).
template <bool SCALED>
__device__ __forceinline__ void chunk1t(uint32_t sbase, uint32_t aOff, uint32_t bOff,
                                        float acc[2][8][4],
                                        const __half2* ga, const __half2* gb) {
#pragma unroll
    for (int ks = 0; ks < 2; ks++) {
        uint32_t a[2][4], b[8][2];
#pragma unroll
        for (int mf = 0; mf < 2; mf++) {
            ldsm4(sbase + aOff + mf * 1280 + ks * 32, a[mf]);
            if (SCALED) {
                __half2* ap = reinterpret_cast<__half2*>(a[mf]);
                ap[0] = __hmul2(ap[0], ga[mf]);
                ap[2] = __hmul2(ap[2], ga[mf]);
                ap[1] = __hmul2(ap[1], gb[mf]);
                ap[3] = __hmul2(ap[3], gb[mf]);
            }
        }
#pragma unroll
        for (int n2 = 0; n2 < 4; n2++) {
            uint32_t r[4];
            ldsm4t(sbase + 10240 + bOff + (uint32_t)(ks * 16 * 272 + n2 * 32), r);
            b[n2 * 2][0] = r[0]; b[n2 * 2][1] = r[1];
            b[n2 * 2 + 1][0] = r[2]; b[n2 * 2 + 1][1] = r[3];
        }
#pragma unroll
        for (int mf = 0; mf < 2; mf++)
#pragma unroll
            for (int nf = 0; nf < 8; nf++) mmah(acc[mf][nf], a[mf], b[nf]);
    }
}

struct __align__(8) hpair { __half2 a, b; };
__device__ __forceinline__ hpair to_h(float4 v) {
    hpair r; r.a = __floats2half2_rn(v.x, v.y); r.b = __floats2half2_rn(v.z, v.w); return r;
}

// ---------------- cvtw: W fp32 -> fp16 (SCALE folded into Wq) ----------------
__global__ void cvtw_kernel(const float* __restrict__ Wq, const float* __restrict__ Wk,
                            const float* __restrict__ Wv) {
    int i = (blockIdx.x * 256 + threadIdx.x) * 4;
    int z = i / 147456, r = i - z * 147456;
    const float* W = (z == 0) ? Wq : ((z == 1) ? Wk : Wv);
    float4 v = *(const float4*)(W + r);
    float s = (z == 0) ? SCALE : 1.f;
    v.x *= s; v.y *= s; v.z *= s; v.w *= s;
    *(hpair*)&g_Wh[i] = to_h(v);
}

// ---------------- proj: X fp32 (convert in stage) x W fp16, 3-stage pipeline ----------------
__global__ void __launch_bounds__(256, 2) proj_kernel(const float* __restrict__ X) {
    extern __shared__ char smem[];
    int tid = threadIdx.x, lane = tid & 31, wid = tid >> 5, wm = wid & 3, wn = wid >> 2;
    uint32_t sb = smem_u32(smem);
    int nt = blockIdx.x * 128, mt = blockIdx.y * 128, z = blockIdx.z;
    const float*  gA = X + (size_t)mt * 384;
    const __half* gW = g_Wh + (size_t)z * 147456 + nt;
    ACC_DECL();

    float4 va[4]; uint4 wb[2];
    auto ldg = [&](int c) {
#pragma unroll
        for (int i = 0; i < 4; i++) {
            int lin = tid + 256 * i, row = lin >> 3, c4 = (lin & 7) * 4;
            va[i] = ldcg4f(gA + (size_t)row * 384 + c * 32 + c4);
        }
#pragma unroll
        for (int i = 0; i < 2; i++) {
            int lin = tid + 256 * i, r2 = lin >> 4, c2 = (lin & 15) * 8;
            wb[i] = ldcg4(gW + (size_t)(c * 32 + r2) * 384 + c2);
        }
    };
    auto stg = [&](char* buf) {
#pragma unroll
        for (int i = 0; i < 4; i++) {
            int lin = tid + 256 * i, row = lin >> 3, c4 = (lin & 7) * 4;
            *(hpair*)(buf + row * 80 + c4 * 2) = to_h(va[i]);
        }
#pragma unroll
        for (int i = 0; i < 2; i++) {
            int lin = tid + 256 * i, r2 = lin >> 4, c2 = (lin & 15) * 8;
            *(uint4*)(buf + 10240 + r2 * 272 + c2 * 2) = wb[i];
        }
    };
    uint32_t aOff = AOFF(wm, lane), bOff = BOFFT(wn, lane);
    ldg(0); stg(smem); ldg(1);
    __syncthreads();
    int rs = 0;
    for (int c = 0; c < 12; c++) {
        int ws = (rs == 2) ? 0 : rs + 1;
        if (c + 1 < 12) stg(smem + ws * STG_T);
        if (c + 2 < 12) ldg(c + 2);
        chunk1t<false>(sb + (uint32_t)(rs * STG_T), aOff, bOff, acc, 0, 0);
        __syncthreads();
        rs = ws;
    }

    __half* Yh = (z == 0) ? g_Qh : ((z == 1) ? g_Kh : g_Vh);
#pragma unroll
    for (int mf = 0; mf < 2; mf++)
#pragma unroll
        for (int h = 0; h < 2; h++) {
            int row = mt + wm * 32 + mf * 16 + (lane >> 2) + h * 8;
#pragma unroll
            for (int nf = 0; nf < 8; nf++) {
                int col = nt + wn * 64 + nf * 8 + (lane & 3) * 2;
                *(__half2*)&Yh[(size_t)row * 384 + col] =
                    __floats2half2_rn(acc[mf][nf][h * 2], acc[mf][nf][h * 2 + 1]);
            }
        }
}

// ---------------- qk: 3-stage pipeline + fused local softmax (R11-proven) ----------------
__global__ void __launch_bounds__(256, 2) qk_kernel() {
    extern __shared__ char smem[];
    int tid = threadIdx.x, lane = tid & 31, wid = tid >> 5, wm = wid & 3, wn = wid >> 2;
    uint32_t sb = smem_u32(smem);
    int b = blockIdx.y, r_ = blockIdx.x, qt = 0;
    while (r_ > qt) { r_ -= qt + 1; qt++; }
    int kt = r_;
    size_t qb = ((size_t)b * 2048 + qt * 128) * 384;
    size_t kb = ((size_t)b * 2048 + kt * 128) * 384;
    ACC_DECL();

    uint4 rv[4];
    auto ldg = [&](int c) {
#pragma unroll
        for (int i = 0; i < 2; i++) {
            int lin = tid + 256 * i, rr = lin >> 2, cc = (lin & 3) * 8;
            size_t o = (size_t)rr * 384 + c * 32 + cc;
            rv[i * 2 + 0] = ldcg4(g_Qh + qb + o);
            rv[i * 2 + 1] = ldcg4(g_Kh + kb + o);
        }
    };
    auto stg = [&](char* buf) {
#pragma unroll
        for (int i = 0; i < 2; i++) {
            int lin = tid + 256 * i, rr = lin >> 2, cc = (lin & 3) * 8;
            int o = rr * 80 + cc * 2;
            *(uint4*)(buf + o)         = rv[i * 2 + 0];
            *(uint4*)(buf + 10240 + o) = rv[i * 2 + 1];
        }
    };
    uint32_t aOff = AOFF(wm, lane), bOff = BOFF(wn, lane);
    ldg(0); stg(smem); ldg(1);
    __syncthreads();
    int rs = 0;
    for (int c = 0; c < 12; c++) {
        int ws = (rs == 2) ? 0 : rs + 1;
        if (c + 1 < 12) stg(smem + ws * STG_QK);
        if (c + 2 < 12) ldg(c + 2);
        chunk1(sb + (uint32_t)(rs * STG_QK), aOff, bOff, acc);
        __syncthreads();
        rs = ws;
    }

    // ---- fused epilogue: mask, local max, exp, row sums, P~ store ----
    float* sR = (float*)smem;
    float pm[2][2] = {{-1e30f, -1e30f}, {-1e30f, -1e30f}};
#pragma unroll
    for (int mf = 0; mf < 2; mf++)
#pragma unroll
        for (int nf = 0; nf < 8; nf++)
#pragma unroll
            for (int q = 0; q < 4; q++) {
                int h = q >> 1;
                int qg = qt * 128 + wm * 32 + mf * 16 + (lane >> 2) + h * 8;
                int kg = kt * 128 + wn * 64 + nf * 8 + (lane & 3) * 2 + (q & 1);
                if (kg > qg) acc[mf][nf][q] = -1e30f;
                pm[mf][h] = fmaxf(pm[mf][h], acc[mf][nf][q]);
            }
#pragma unroll
    for (int mf = 0; mf < 2; mf++)
#pragma unroll
        for (int h = 0; h < 2; h++) {
            pm[mf][h] = fmaxf(pm[mf][h], __shfl_xor_sync(~0u, pm[mf][h], 1));
            pm[mf][h] = fmaxf(pm[mf][h], __shfl_xor_sync(~0u, pm[mf][h], 2));
        }
    int rl[2][2];
#pragma unroll
    for (int mf = 0; mf < 2; mf++)
#pragma unroll
        for (int h = 0; h < 2; h++)
            rl[mf][h] = wm * 32 + mf * 16 + (lane >> 2) + h * 8;
    if ((lane & 3) == 0)
#pragma unroll
        for (int mf = 0; mf < 2; mf++)
#pragma unroll
            for (int h = 0; h < 2; h++) sR[wn * 128 + rl[mf][h]] = pm[mf][h];
    __syncthreads();
    float mrow[2][2], ps[2][2] = {{0.f, 0.f}, {0.f, 0.f}};
#pragma unroll
    for (int mf = 0; mf < 2; mf++)
#pragma unroll
        for (int h = 0; h < 2; h++) mrow[mf][h] = fmaxf(sR[rl[mf][h]], sR[128 + rl[mf][h]]);
#pragma unroll
    for (int mf = 0; mf < 2; mf++)
#pragma unroll
        for (int nf = 0; nf < 8; nf++)
#pragma unroll
            for (int q = 0; q < 4; q++) {
                int h = q >> 1;
                float p = __expf(acc[mf][nf][q] - mrow[mf][h]);
                acc[mf][nf][q] = p;
                ps[mf][h] += p;
            }
#pragma unroll
    for (int mf = 0; mf < 2; mf++)
#pragma unroll
        for (int h = 0; h < 2; h++) {
            ps[mf][h] += __shfl_xor_sync(~0u, ps[mf][h], 1);
            ps[mf][h] += __shfl_xor_sync(~0u, ps[mf][h], 2);
        }
    __syncthreads();
    if ((lane & 3) == 0)
#pragma unroll
        for (int mf = 0; mf < 2; mf++)
#pragma unroll
            for (int h = 0; h < 2; h++) sR[wn * 128 + rl[mf][h]] = ps[mf][h];
    __syncthreads();
    size_t statb = ((size_t)(b * 16 + qt) * 16 + kt) * 128;
    if (wn == 0 && (lane & 3) == 0)
#pragma unroll
        for (int mf = 0; mf < 2; mf++)
#pragma unroll
            for (int h = 0; h < 2; h++) {
                g_mt[statb + rl[mf][h]] = mrow[mf][h];
                g_lt[statb + rl[mf][h]] = sR[rl[mf][h]] + sR[128 + rl[mf][h]];
            }
    __half* Prow = g_Pt + ((size_t)b * 2048 + qt * 128) * 2048 + (size_t)kt * 128;
#pragma unroll
    for (int mf = 0; mf < 2; mf++)
#pragma unroll
        for (int h = 0; h < 2; h++) {
#pragma unroll
            for (int nf = 0; nf < 8; nf++) {
                int col = wn * 64 + nf * 8 + (lane & 3) * 2;
                *(__half2*)&Prow[(size_t)rl[mf][h] * 2048 + col] =
                    __floats2half2_rn(acc[mf][nf][h * 2], acc[mf][nf][h * 2 + 1]);
            }
        }
}

// ---------------- norm: fold M and 1/l into per-tile row factors ----------------
__global__ void __launch_bounds__(128) norm_kernel() {
    int bq = blockIdx.x;                // b*16 + qt
    int qt = bq & 15, row = threadIdx.x;
    int ntl = qt + 1;
    size_t base = (size_t)bq * 16 * 128 + row;
    float m = -1e30f;
    for (int t = 0; t < ntl; t++) m = fmaxf(m, g_mt[base + t * 128]);
    float l = 0.f;
    for (int t = 0; t < ntl; t++) l += __expf(g_mt[base + t * 128] - m) * g_lt[base + t * 128];
    float inv = 1.f / l;
    for (int t = 0; t < ntl; t++) g_g[base + t * 128] = __expf(g_mt[base + t * 128] - m) * inv;
}

// ---------------- pv: 3-stage pipeline; sg bulk-loaded; g on A fragments ----------------
__global__ void __launch_bounds__(256, 2) pv_kernel(float* __restrict__ out) {
    extern __shared__ char smem[];
    int tid = threadIdx.x, lane = tid & 31, wid = tid >> 5, wm = wid & 3, wn = wid >> 2;
    uint32_t sb = smem_u32(smem);
    int nt = blockIdx.x * 128, qt = 15 - (int)blockIdx.y, b = blockIdx.z;
    int nch = (qt + 1) * 4;
    const __half* Pb = g_Pt + ((size_t)b * 2048 + qt * 128) * 2048;
    const __half* Vh = g_Vh + (size_t)b * 2048 * 384 + nt;
    const size_t statb = (size_t)(b * 16 + qt) * 16 * 128;
    float* sg = (float*)(smem + SMEM_T3);        // [16 tiles][128 rows]
    ACC_DECL();

    uint4 rv[4];
    auto ldg = [&](int c) {
#pragma unroll
        for (int i = 0; i < 2; i++) {
            int lin = tid + 256 * i;
            int rr = lin >> 2, cc = (lin & 3) * 8;            // A: 128 x 32
            rv[i * 2 + 0] = ldcg4(Pb + (size_t)rr * 2048 + c * 32 + cc);
            int r2 = lin >> 4, c2 = (lin & 15) * 8;           // B: 32 x 128
            rv[i * 2 + 1] = ldcg4(Vh + (size_t)(c * 32 + r2) * 384 + c2);
        }
    };
    auto stg = [&](char* buf) {
#pragma unroll
        for (int i = 0; i < 2; i++) {
            int lin = tid + 256 * i;
            int rr = lin >> 2, cc = (lin & 3) * 8;
            *(uint4*)(buf + rr * 80 + cc * 2) = rv[i * 2 + 0];
            int r2 = lin >> 4, c2 = (lin & 15) * 8;
            *(uint4*)(buf + 10240 + r2 * 272 + c2 * 2) = rv[i * 2 + 1];
        }
    };
    uint32_t aOff = AOFF(wm, lane), bOff = BOFFT(wn, lane);
    ldg(0);
    // bulk-load precomputed fold factors (coalesced, parallel)
    {
        int ntl = qt + 1;
        for (int i = tid; i < ntl * 128; i += 256) sg[i] = g_g[statb + i];
    }
    stg(smem); ldg(1);
    __syncthreads();

    int rbase = wm * 32 + (lane >> 2);
    int rs = 0;
    __half2 ga[2], gb[2];
    for (int c = 0; c < nch; c++) {
        if ((c & 3) == 0) {
            const float* gp = sg + (c >> 2) * 128;
#pragma unroll
            for (int mf = 0; mf < 2; mf++) {
                ga[mf] = __float2half2_rn(gp[rbase + mf * 16]);
                gb[mf] = __float2half2_rn(gp[rbase + mf * 16 + 8]);
            }
        }
        int ws = (rs == 2) ? 0 : rs + 1;
        if (c + 1 < nch) stg(smem + ws * STG_T);
        if (c + 2 < nch) ldg(c + 2);
        chunk1t<true>(sb + (uint32_t)(rs * STG_T), aOff, bOff, acc, ga, gb);
        __syncthreads();
        rs = ws;
    }

    float* Y = out + ((size_t)b * 2048 + qt * 128) * 384 + nt;
#pragma unroll
    for (int mf = 0; mf < 2; mf++)
#pragma unroll
        for (int h = 0; h < 2; h++) {
            int row = wm * 32 + mf * 16 + (lane >> 2) + h * 8;
#pragma unroll
            for (int nf = 0; nf < 8; nf++) {
                float2 v = make_float2(acc[mf][nf][h * 2], acc[mf][nf][h * 2 + 1]);
                *(float2*)&Y[(size_t)row * 384 + wn * 64 + nf * 8 + (lane & 3) * 2] = v;
            }
        }
}

extern "C" void kernel_launch(void* const* d_in, const int* in_sizes, int n_in,
                              void* d_out, int out_size) {
    const float* x  = (const float*)d_in[0];
    const float* Wq = (const float*)d_in[1];
    const float* Wk = (const float*)d_in[2];
    const float* Wv = (const float*)d_in[3];
    float* out = (float*)d_out;
    (void)in_sizes; (void)n_in; (void)out_size;

    cudaFuncSetAttribute(proj_kernel, cudaFuncAttributeMaxDynamicSharedMemorySize, SMEM_T3);
    cudaFuncSetAttribute(qk_kernel,   cudaFuncAttributeMaxDynamicSharedMemorySize, SMEM_QK3);
    cudaFuncSetAttribute(pv_kernel,   cudaFuncAttributeMaxDynamicSharedMemorySize, SMEM_PV3);

    cvtw_kernel<<<432, 256>>>(Wq, Wk, Wv);
    proj_kernel<<<dim3(3, 256, 3), 256, SMEM_T3>>>(x);
    qk_kernel<<<dim3(136, 16), 256, SMEM_QK3>>>();
    norm_kernel<<<256, 128>>>();
    pv_kernel<<<dim3(3, 16, 16), 256, SMEM_PV3>>>(out);
}